// round 14
// baseline (speedup 1.0000x reference)
#include <cuda_runtime.h>
#include <cuda_bf16.h>
#include <math_constants.h>
#include <mma.h>
#include <cstdint>

using namespace nvcuda;

// ---------------- output packing ----------------
#define LEN_RECON (512*4096)
#define LEN_DIST  (512*64*1024)
#define LEN_IDX   (512*64)
#define LEN_MU    (512*256)
#define LEN_LV    (512*256)
#define LEN_DMU   (512*768)
#define LEN_DLV   (512*768)

#define OFF_RECON 0
#define OFF_DIST  (OFF_RECON + LEN_RECON)
#define OFF_IDX   (OFF_DIST  + LEN_DIST)
#define OFF_MU    (OFF_IDX   + LEN_IDX)
#define OFF_LV    (OFF_MU    + LEN_MU)
#define OFF_DMU   (OFF_LV    + LEN_LV)
#define OFF_DLV   (OFF_DMU   + LEN_DMU)
#define OFF_PLV   (OFF_DLV   + LEN_DLV)

// ---------------- scratch ----------------
__device__ unsigned int g_hmaxu[512 * 512];
__device__ float g_h2[512 * 2048];
__device__ float g_h3[512 * 512];
__device__ float g_t[512 * 2048];
__device__ float g_tp[512 * 2048];
__device__ float g_p[512 * 1536];
__device__ float g_xr2[512 * 64];
__device__ float g_book2[64 * 1024];
__device__ unsigned long long g_keys[512 * 64];

__device__ __forceinline__ unsigned int f32_ordered(float f)
{
    unsigned int b = __float_as_uint(f);
    return (b & 0x80000000u) ? ~b : (b | 0x80000000u);
}
__device__ __forceinline__ float f32_unordered(unsigned int u)
{
    return __uint_as_float((u & 0x80000000u) ? (u & 0x7FFFFFFFu) : ~u);
}

// ================ 128x64 blocks (256 thr, 8 warps, 32x32 warp tile) ====
#define BMt 128
#define BNt 64
#define BKt 32
#define PADt 40
#define STG_BYTES 30720
#define GEMM_SMEM 61440

#define AHI(s) (reinterpret_cast<__nv_bfloat16*>(smem + (s) * STG_BYTES))
#define ALO(s) (AHI(s) + BMt * PADt)
#define BHI(s) (ALO(s) + BMt * PADt)
#define BLO(s) (BHI(s) + BNt * PADt)

#define CVT_ST(hiP, loP, r, v)                                                 \
    {                                                                          \
        __nv_bfloat16 hx = __float2bfloat16((v).x);                            \
        __nv_bfloat16 hy = __float2bfloat16((v).y);                            \
        __nv_bfloat16 hz = __float2bfloat16((v).z);                            \
        __nv_bfloat16 hw = __float2bfloat16((v).w);                            \
        __nv_bfloat16* ph = (hiP) + (r) * PADt + ak4 * 4;                      \
        *reinterpret_cast<__nv_bfloat162*>(ph)     = __halves2bfloat162(hx, hy); \
        *reinterpret_cast<__nv_bfloat162*>(ph + 2) = __halves2bfloat162(hz, hw); \
        __nv_bfloat16* pl = (loP) + (r) * PADt + ak4 * 4;                      \
        *reinterpret_cast<__nv_bfloat162*>(pl) = __halves2bfloat162(           \
            __float2bfloat16((v).x - __bfloat162float(hx)),                    \
            __float2bfloat16((v).y - __bfloat162float(hy)));                   \
        *reinterpret_cast<__nv_bfloat162*>(pl + 2) = __halves2bfloat162(       \
            __float2bfloat16((v).z - __bfloat162float(hz)),                    \
            __float2bfloat16((v).w - __bfloat162float(hw)));                   \
    }

#define MMA_BLOCK(pp)                                                          \
    _Pragma("unroll")                                                          \
    for (int kk = 0; kk < BKt; kk += 16) {                                     \
        wmma::fragment<wmma::matrix_a, 16, 16, 16, __nv_bfloat16, wmma::row_major> ah[2], al[2]; \
        wmma::fragment<wmma::matrix_b, 16, 16, 16, __nv_bfloat16, wmma::col_major> bh[2], bl[2]; \
        _Pragma("unroll")                                                      \
        for (int i = 0; i < 2; i++) {                                          \
            const __nv_bfloat16* pa = AHI(pp) + (wm * 32 + i * 16) * PADt + kk; \
            wmma::load_matrix_sync(ah[i], pa, PADt);                           \
            wmma::load_matrix_sync(al[i], pa + BMt * PADt, PADt);              \
        }                                                                      \
        _Pragma("unroll")                                                      \
        for (int j = 0; j < 2; j++) {                                          \
            const __nv_bfloat16* pb = BHI(pp) + (wn * 32 + j * 16) * PADt + kk; \
            wmma::load_matrix_sync(bh[j], pb, PADt);                           \
            wmma::load_matrix_sync(bl[j], pb + BNt * PADt, PADt);              \
        }                                                                      \
        _Pragma("unroll")                                                      \
        for (int i = 0; i < 2; i++)                                            \
            _Pragma("unroll")                                                  \
            for (int j = 0; j < 2; j++) {                                      \
                wmma::mma_sync(acc[i][j], ah[i], bh[j], acc[i][j]);            \
                wmma::mma_sync(acc[i][j], ah[i], bl[j], acc[i][j]);            \
                wmma::mma_sync(acc[i][j], al[i], bh[j], acc[i][j]);            \
            }                                                                  \
    }

// ================= templated GEMM =================
// MODE:  0 C ; 1 maxpool->mp ; 2 C+mu/lv ; 3 C+plv ; 4 dmu/dlv only ; 5 C+xr2
// AMODE: 0 plain ; 1 ordered-uint decode ; 2 concat(A|A2)@256 ; 3 A+A2
template<int MODE, int AMODE>
__global__ __launch_bounds__(256) void k_wgemm(
    const float* __restrict__ Ap, int lda,
    const float* __restrict__ Ap2, int lda2,
    const float* __restrict__ Wp, int K,
    const float* __restrict__ bias,
    float* __restrict__ C, int N, int act,
    float* __restrict__ aux0, float* __restrict__ aux1)
{
    extern __shared__ char smem[];
    const int tid = threadIdx.x, wid = tid >> 5, lid = tid & 31;
    const int bm = blockIdx.y * BMt, bn = blockIdx.x * BNt;
    const int wm = wid & 3, wn = wid >> 2;
    const int arow = tid >> 3, ak4 = tid & 7;
    const int ldw = K;

    float4 ar[4], br[2];

    auto load_regs = [&](int k0) {
        const int col = k0 + ak4 * 4;
        if constexpr (AMODE == 2) {
#pragma unroll
            for (int i = 0; i < 4; i++) {
                int m = bm + arow + i * 32;
                const float* src = (col < 256) ? &Ap[(size_t)m * lda + col]
                                               : &Ap2[(size_t)m * lda2 + col - 256];
                ar[i] = *reinterpret_cast<const float4*>(src);
            }
        } else if constexpr (AMODE == 3) {
#pragma unroll
            for (int i = 0; i < 4; i++) {
                int m = bm + arow + i * 32;
                float4 u = *reinterpret_cast<const float4*>(&Ap[(size_t)m * lda + col]);
                float4 w2 = *reinterpret_cast<const float4*>(&Ap2[(size_t)m * lda2 + col]);
                ar[i] = make_float4(u.x + w2.x, u.y + w2.y, u.z + w2.z, u.w + w2.w);
            }
        } else {
#pragma unroll
            for (int i = 0; i < 4; i++)
                ar[i] = *reinterpret_cast<const float4*>(
                    &Ap[(size_t)(bm + arow + i * 32) * lda + col]);
            if constexpr (AMODE == 1) {
#pragma unroll
                for (int i = 0; i < 4; i++) {
                    ar[i].x = f32_unordered(__float_as_uint(ar[i].x));
                    ar[i].y = f32_unordered(__float_as_uint(ar[i].y));
                    ar[i].z = f32_unordered(__float_as_uint(ar[i].z));
                    ar[i].w = f32_unordered(__float_as_uint(ar[i].w));
                }
            }
        }
#pragma unroll
        for (int i = 0; i < 2; i++)
            br[i] = *reinterpret_cast<const float4*>(
                &Wp[(size_t)(bn + arow + i * 32) * ldw + col]);
    };

    auto stage = [&](int s) {
#pragma unroll
        for (int i = 0; i < 4; i++) CVT_ST(AHI(s), ALO(s), arow + i * 32, ar[i]);
#pragma unroll
        for (int i = 0; i < 2; i++) CVT_ST(BHI(s), BLO(s), arow + i * 32, br[i]);
    };

    wmma::fragment<wmma::accumulator, 16, 16, 16, float> acc[2][2];
#pragma unroll
    for (int i = 0; i < 2; i++)
#pragma unroll
        for (int j = 0; j < 2; j++)
            wmma::fill_fragment(acc[i][j], 0.0f);

    const int nt = K / BKt;
    load_regs(0);
    stage(0);
    __syncthreads();
    for (int t = 0; t < nt; t++) {
        const int pp = t & 1;
        if (t + 1 < nt) load_regs((t + 1) * BKt);
        MMA_BLOCK(pp);
        if (t + 1 < nt) stage(1 - pp);
        __syncthreads();
    }

    float* patch = reinterpret_cast<float*>(smem) + wid * 1024;
#pragma unroll
    for (int i = 0; i < 2; i++)
#pragma unroll
        for (int j = 0; j < 2; j++)
            wmma::store_matrix_sync(patch + i * 16 * 32 + j * 16, acc[i][j], 32,
                                    wmma::mem_row_major);
    __syncwarp();

    const int cbase = bn + wn * 32;
    const int c0 = (lid & 7) * 4;

    if constexpr (MODE == 1) {
        unsigned int* mp = reinterpret_cast<unsigned int*>(aux0);
        float mx[4] = {-CUDART_INF_F, -CUDART_INF_F, -CUDART_INF_F, -CUDART_INF_F};
#pragma unroll
        for (int it = 0; it < 8; it++) {
            int r = it * 4 + (lid >> 3);
#pragma unroll
            for (int j = 0; j < 4; j++) {
                float rr = patch[r * 32 + c0 + j] + __ldg(&bias[cbase + c0 + j]);
                rr = rr > 0.f ? rr : 0.2f * rr;
                mx[j] = fmaxf(mx[j], rr);
            }
        }
        int b = (bm + wm * 32) >> 6;
#pragma unroll
        for (int j = 0; j < 4; j++)
            atomicMax(&mp[b * N + cbase + c0 + j], f32_ordered(mx[j]));
        return;
    }

#pragma unroll
    for (int it = 0; it < 8; it++) {
        int r = it * 4 + (lid >> 3);
        int m = bm + wm * 32 + r;
        int n = cbase + c0;
        float4 v;
        float* vp = reinterpret_cast<float*>(&v);
#pragma unroll
        for (int j = 0; j < 4; j++) {
            float rr = patch[r * 32 + c0 + j] + __ldg(&bias[n + j]);
            if (act) rr = rr > 0.f ? rr : 0.2f * rr;
            vp[j] = rr;
        }
        if constexpr (MODE != 4)
            *reinterpret_cast<float4*>(&C[(size_t)m * N + n]) = v;
        if constexpr (MODE == 2) {
            if (n < 256)
                *reinterpret_cast<float4*>(&aux0[m * 256 + n]) = v;
            else
                *reinterpret_cast<float4*>(&aux1[m * 256 + n - 256]) = v;
        } else if constexpr (MODE == 3) {
            if (n >= 768)
                *reinterpret_cast<float4*>(&aux0[m * 768 + n - 768]) = v;
        } else if constexpr (MODE == 4) {
            if (n < 768)
                *reinterpret_cast<float4*>(&aux0[m * 768 + n]) = v;
            else
                *reinterpret_cast<float4*>(&aux1[m * 768 + n - 768]) = v;
        } else if constexpr (MODE == 5) {
            float sq = v.x * v.x + v.y * v.y + v.z * v.z + v.w * v.w;
#pragma unroll
            for (int off = 4; off; off >>= 1)
                sq += __shfl_xor_sync(0xffffffffu, sq, off, 8);
            if ((lid & 7) == 0)
                atomicAdd(&aux0[m * 64 + (bn >> 6)], sq);
        }
    }
}

// ================= tensorized dist + argmin (R10-identical) =================
__global__ __launch_bounds__(256) void k_distw(
    const float* __restrict__ recon,
    const float* __restrict__ book,
    const float* __restrict__ xr2,
    const float* __restrict__ book2,
    float* __restrict__ dist,
    unsigned long long* __restrict__ keys)
{
    extern __shared__ char smem[];

    const int tid = threadIdx.x, wid = tid >> 5, lid = tid & 31;
    const int c = blockIdx.z;
    const int bm = blockIdx.y * BMt, bn = blockIdx.x * BNt;
    const int wm = wid & 3, wn = wid >> 2;
    const int arow = tid >> 3, ak4 = tid & 7;

    const float* Ap = recon + c * 64;
    const float* Wp = book + (size_t)c * 65536;
    const int lda = 4096, ldw = 64;

    float4 ar[4], br[2];

    auto load_regs = [&](int k0) {
#pragma unroll
        for (int i = 0; i < 4; i++)
            ar[i] = *reinterpret_cast<const float4*>(
                &Ap[(size_t)(bm + arow + i * 32) * lda + k0 + ak4 * 4]);
#pragma unroll
        for (int i = 0; i < 2; i++)
            br[i] = *reinterpret_cast<const float4*>(
                &Wp[(size_t)(bn + arow + i * 32) * ldw + k0 + ak4 * 4]);
    };
    auto stage = [&](int s) {
#pragma unroll
        for (int i = 0; i < 4; i++) CVT_ST(AHI(s), ALO(s), arow + i * 32, ar[i]);
#pragma unroll
        for (int i = 0; i < 2; i++) CVT_ST(BHI(s), BLO(s), arow + i * 32, br[i]);
    };

    wmma::fragment<wmma::accumulator, 16, 16, 16, float> acc[2][2];
#pragma unroll
    for (int i = 0; i < 2; i++)
#pragma unroll
        for (int j = 0; j < 2; j++)
            wmma::fill_fragment(acc[i][j], 0.0f);

    const int nt = 2;
    load_regs(0);
    stage(0);
    __syncthreads();
    for (int t = 0; t < nt; t++) {
        const int pp = t & 1;
        if (t + 1 < nt) load_regs((t + 1) * BKt);
        MMA_BLOCK(pp);
        if (t + 1 < nt) stage(1 - pp);
        __syncthreads();
    }

    float* patch = reinterpret_cast<float*>(smem) + wid * 1024;
#pragma unroll
    for (int i = 0; i < 2; i++)
#pragma unroll
        for (int j = 0; j < 2; j++)
            wmma::store_matrix_sync(patch + i * 16 * 32 + j * 16, acc[i][j], 32,
                                    wmma::mem_row_major);
    __syncwarp();

    const int sbase = bn + wn * 32;
    const int c0 = (lid & 7) * 4;

#pragma unroll
    for (int it = 0; it < 8; it++) {
        int r = it * 4 + (lid >> 3);
        int m = bm + wm * 32 + r;
        int s = sbase + c0;
        float x2 = __ldg(&xr2[m * 64 + c]);
        float4 v;
        float* vp = reinterpret_cast<float*>(&v);
        unsigned long long kbest = ~0ull;
#pragma unroll
        for (int j = 0; j < 4; j++) {
            float dval = x2 + __ldg(&book2[c * 1024 + s + j])
                       - 2.0f * patch[r * 32 + c0 + j];
            vp[j] = dval;
            unsigned long long key =
                ((unsigned long long)f32_ordered(dval) << 32) | (unsigned int)(s + j);
            kbest = min(kbest, key);
        }
        *reinterpret_cast<float4*>(&dist[((size_t)m * 64 + c) * 1024 + s]) = v;
#pragma unroll
        for (int off = 4; off; off >>= 1) {
            unsigned long long o = __shfl_xor_sync(0xffffffffu, kbest, off, 8);
            kbest = min(kbest, o);
        }
        if ((lid & 7) == 0) atomicMin(&keys[m * 64 + c], kbest);
    }
}

// ================= init + writeidx =================
__global__ void k_init(unsigned int* __restrict__ hmaxu,
                       unsigned long long* __restrict__ keys,
                       const float* __restrict__ book,
                       float* __restrict__ book2,
                       float* __restrict__ xr2)
{
    int idx = blockIdx.x * blockDim.x + threadIdx.x;
    if (idx < 512 * 512) hmaxu[idx] = f32_ordered(-CUDART_INF_F);
    if (idx < 512 * 64)  { keys[idx] = ~0ull; xr2[idx] = 0.f; }
    if (idx < 64 * 1024) {
        const float4* p = reinterpret_cast<const float4*>(book + (size_t)idx * 64);
        float s = 0.f;
#pragma unroll
        for (int i = 0; i < 16; i++) {
            float4 v = p[i];
            s += v.x * v.x + v.y * v.y + v.z * v.z + v.w * v.w;
        }
        book2[idx] = s;
    }
}

__global__ void k_writeidx(const unsigned long long* __restrict__ keys,
                           float* __restrict__ out)
{
    int idx = blockIdx.x * blockDim.x + threadIdx.x;
    if (idx < 512 * 64)
        out[idx] = (float)(unsigned int)(keys[idx] & 0xFFFFFFFFull);
}

// ================= launcher =================
extern "C" void kernel_launch(void* const* d_in, const int* in_sizes, int n_in,
                              void* d_out, int out_size)
{
    const float* x        = (const float*)d_in[0];
    const float* codebook = (const float*)d_in[1];
    const float* enc_w1   = (const float*)d_in[2];
    const float* enc_b1   = (const float*)d_in[3];
    const float* enc_w2   = (const float*)d_in[4];
    const float* enc_b2   = (const float*)d_in[5];
    const float* inf1_w   = (const float*)d_in[6];
    const float* inf1_b   = (const float*)d_in[7];
    const float* inf2_w1  = (const float*)d_in[8];
    const float* inf2_b1  = (const float*)d_in[9];
    const float* inf2_w2  = (const float*)d_in[10];
    const float* inf2_b2  = (const float*)d_in[11];
    const float* prior_w1 = (const float*)d_in[12];
    const float* prior_b1 = (const float*)d_in[13];
    const float* prior_w2 = (const float*)d_in[14];
    const float* prior_b2 = (const float*)d_in[15];
    const float* dec_w1   = (const float*)d_in[16];
    const float* dec_b1   = (const float*)d_in[17];
    const float* dec_w2   = (const float*)d_in[18];
    const float* dec_b2   = (const float*)d_in[19];
    float* out = (float*)d_out;

    float *h2, *h3, *t, *tp, *p, *xr2, *book2;
    unsigned int* hmaxu;
    unsigned long long* keys;
    cudaGetSymbolAddress((void**)&hmaxu, g_hmaxu);
    cudaGetSymbolAddress((void**)&h2,    g_h2);
    cudaGetSymbolAddress((void**)&h3,    g_h3);
    cudaGetSymbolAddress((void**)&t,     g_t);
    cudaGetSymbolAddress((void**)&tp,    g_tp);
    cudaGetSymbolAddress((void**)&p,     g_p);
    cudaGetSymbolAddress((void**)&xr2,   g_xr2);
    cudaGetSymbolAddress((void**)&book2, g_book2);
    cudaGetSymbolAddress((void**)&keys,  g_keys);

    cudaFuncSetAttribute(k_wgemm<1,0>, cudaFuncAttributeMaxDynamicSharedMemorySize, GEMM_SMEM);
    cudaFuncSetAttribute(k_wgemm<0,1>, cudaFuncAttributeMaxDynamicSharedMemorySize, GEMM_SMEM);
    cudaFuncSetAttribute(k_wgemm<2,0>, cudaFuncAttributeMaxDynamicSharedMemorySize, GEMM_SMEM);
    cudaFuncSetAttribute(k_wgemm<0,0>, cudaFuncAttributeMaxDynamicSharedMemorySize, GEMM_SMEM);
    cudaFuncSetAttribute(k_wgemm<3,0>, cudaFuncAttributeMaxDynamicSharedMemorySize, GEMM_SMEM);
    cudaFuncSetAttribute(k_wgemm<0,2>, cudaFuncAttributeMaxDynamicSharedMemorySize, GEMM_SMEM);
    cudaFuncSetAttribute(k_wgemm<4,0>, cudaFuncAttributeMaxDynamicSharedMemorySize, GEMM_SMEM);
    cudaFuncSetAttribute(k_wgemm<0,3>, cudaFuncAttributeMaxDynamicSharedMemorySize, GEMM_SMEM);
    cudaFuncSetAttribute(k_wgemm<5,0>, cudaFuncAttributeMaxDynamicSharedMemorySize, GEMM_SMEM);
    cudaFuncSetAttribute(k_distw,      cudaFuncAttributeMaxDynamicSharedMemorySize, GEMM_SMEM);

    const float* hmaxf = (const float*)hmaxu;

    // 0) fused init
    k_init<<<(512*512+255)/256, 256>>>(hmaxu, keys, codebook, book2, xr2);
    // 1) enc1 + fused maxpool (2048 CTAs)
    k_wgemm<1,0><<<dim3(8, 256), 256, GEMM_SMEM>>>(
        x, 64, nullptr, 0, enc_w1, 64, enc_b1, nullptr, 512, 1, (float*)hmaxu, nullptr);
    // 2) enc2 (ordered-uint decode of hmaxu)
    k_wgemm<0,1><<<dim3(32, 4), 256, GEMM_SMEM>>>(
        hmaxf, 512, nullptr, 0, enc_w2, 512, enc_b2, h2, 2048, 0, nullptr, nullptr);
    // 3) inf1 (+ mu/lv)
    k_wgemm<2,0><<<dim3(8, 4), 256, GEMM_SMEM>>>(
        h2, 2048, nullptr, 0, inf1_w, 2048, inf1_b, h3, 512, 0,
        out + OFF_MU, out + OFF_LV);
    // 4) prior1
    k_wgemm<0,0><<<dim3(32, 4), 256, GEMM_SMEM>>>(
        h3, 512, nullptr, 0, prior_w1, 256, prior_b1, tp, 2048, 1, nullptr, nullptr);
    // 5) prior2 (p + plv)
    k_wgemm<3,0><<<dim3(24, 4), 256, GEMM_SMEM>>>(
        tp, 2048, nullptr, 0, prior_w2, 2048, prior_b2, p, 1536, 0,
        out + OFF_PLV, nullptr);
    // 6) inf2_1 (concat loader [h3|h2])
    k_wgemm<0,2><<<dim3(32, 4), 256, GEMM_SMEM>>>(
        h3, 512, h2, 2048, inf2_w1, 2304, inf2_b1, t, 2048, 1, nullptr, nullptr);
    // 7) inf2_2 (dmu/dlv only)
    k_wgemm<4,0><<<dim3(24, 4), 256, GEMM_SMEM>>>(
        t, 2048, nullptr, 0, inf2_w2, 2048, inf2_b2, nullptr, 1536, 0,
        out + OFF_DMU, out + OFF_DLV);
    // 8) dec1 (A = d_mu + p_mu via sum loader)
    k_wgemm<0,3><<<dim3(32, 4), 256, GEMM_SMEM>>>(
        out + OFF_DMU, 768, p, 1536, dec_w1, 768, dec_b1, tp, 2048, 1, nullptr, nullptr);
    // 9) dec2 (recon + fused xr2)
    k_wgemm<5,0><<<dim3(64, 4), 256, GEMM_SMEM>>>(
        tp, 2048, nullptr, 0, dec_w2, 2048, dec_b2, out + OFF_RECON, 4096, 0,
        xr2, nullptr);
    // 10) dist + argmin
    k_distw<<<dim3(16, 4, 64), 256, GEMM_SMEM>>>(
        out + OFF_RECON, codebook, xr2, book2, out + OFF_DIST, keys);
    // 11) idx
    k_writeidx<<<(512*64+255)/256, 256>>>(keys, out + OFF_IDX);
}

// round 15
// speedup vs baseline: 1.1902x; 1.1902x over previous
#include <cuda_runtime.h>
#include <cuda_bf16.h>
#include <math_constants.h>
#include <mma.h>
#include <cstdint>

using namespace nvcuda;

// ---------------- output packing ----------------
#define LEN_RECON (512*4096)
#define LEN_DIST  (512*64*1024)
#define LEN_IDX   (512*64)
#define LEN_MU    (512*256)
#define LEN_LV    (512*256)
#define LEN_DMU   (512*768)
#define LEN_DLV   (512*768)

#define OFF_RECON 0
#define OFF_DIST  (OFF_RECON + LEN_RECON)
#define OFF_IDX   (OFF_DIST  + LEN_DIST)
#define OFF_MU    (OFF_IDX   + LEN_IDX)
#define OFF_LV    (OFF_MU    + LEN_MU)
#define OFF_DMU   (OFF_LV    + LEN_LV)
#define OFF_DLV   (OFF_DMU   + LEN_DMU)
#define OFF_PLV   (OFF_DLV   + LEN_DLV)

// ---------------- scratch ----------------
__device__ unsigned int g_hmaxu[512 * 512];
__device__ float g_hmax[512 * 512];
__device__ float g_h2[512 * 2048];
__device__ float g_h3[512 * 512];
__device__ float g_t[512 * 2048];
__device__ float g_p[512 * 1536];
__device__ float g_cat[512 * 2304];
__device__ float g_z2[512 * 768];
__device__ float g_xr2[512 * 64];
__device__ float g_book2[64 * 1024];
__device__ unsigned long long g_keys[512 * 64];

__device__ __forceinline__ unsigned int f32_ordered(float f)
{
    unsigned int b = __float_as_uint(f);
    return (b & 0x80000000u) ? ~b : (b | 0x80000000u);
}
__device__ __forceinline__ float f32_unordered(unsigned int u)
{
    return __uint_as_float((u & 0x80000000u) ? (u & 0x7FFFFFFFu) : ~u);
}

// ================ GEMM building blocks (256 thr, 8 warps, 32x32 warp tile) ====
// double-buffered smem stages
#define BMt 128
#define BNt 64
#define BKt 32
#define PADt 40
#define STG_BYTES 30720   // per stage: (128+64)*40*2B*2(hi+lo)

#define AHI(s) (reinterpret_cast<__nv_bfloat16*>(smem + (s) * STG_BYTES))
#define ALO(s) (AHI(s) + BMt * PADt)
#define BHI(s) (ALO(s) + BMt * PADt)
#define BLO(s) (BHI(s) + BNt * PADt)

#define LOAD_REGS(k0)                                                          \
    {                                                                          \
        _Pragma("unroll")                                                      \
        for (int i = 0; i < 4; i++)                                            \
            ar[i] = *reinterpret_cast<const float4*>(                          \
                &Ap[(size_t)(bm + arow + i * 32) * lda + (k0) + ak4 * 4]);     \
        _Pragma("unroll")                                                      \
        for (int i = 0; i < 2; i++)                                            \
            br[i] = *reinterpret_cast<const float4*>(                          \
                &Wp[(size_t)(bn + arow + i * 32) * ldw + (k0) + ak4 * 4]);     \
    }

#define CVT_ST(hiP, loP, r, v)                                                 \
    {                                                                          \
        __nv_bfloat16 hx = __float2bfloat16((v).x);                            \
        __nv_bfloat16 hy = __float2bfloat16((v).y);                            \
        __nv_bfloat16 hz = __float2bfloat16((v).z);                            \
        __nv_bfloat16 hw = __float2bfloat16((v).w);                            \
        __nv_bfloat16* ph = (hiP) + (r) * PADt + ak4 * 4;                      \
        *reinterpret_cast<__nv_bfloat162*>(ph)     = __halves2bfloat162(hx, hy); \
        *reinterpret_cast<__nv_bfloat162*>(ph + 2) = __halves2bfloat162(hz, hw); \
        __nv_bfloat16* pl = (loP) + (r) * PADt + ak4 * 4;                      \
        *reinterpret_cast<__nv_bfloat162*>(pl) = __halves2bfloat162(           \
            __float2bfloat16((v).x - __bfloat162float(hx)),                    \
            __float2bfloat16((v).y - __bfloat162float(hy)));                   \
        *reinterpret_cast<__nv_bfloat162*>(pl + 2) = __halves2bfloat162(       \
            __float2bfloat16((v).z - __bfloat162float(hz)),                    \
            __float2bfloat16((v).w - __bfloat162float(hw)));                   \
    }

#define STAGE(s)                                                               \
    {                                                                          \
        _Pragma("unroll")                                                      \
        for (int i = 0; i < 4; i++) CVT_ST(AHI(s), ALO(s), arow + i * 32, ar[i]); \
        _Pragma("unroll")                                                      \
        for (int i = 0; i < 2; i++) CVT_ST(BHI(s), BLO(s), arow + i * 32, br[i]); \
    }

#define MAINLOOP()                                                             \
    LOAD_REGS(0);                                                              \
    STAGE(0);                                                                  \
    __syncthreads();                                                           \
    for (int t = 0; t < nt; t++) {                                             \
        const int pp = t & 1;                                                  \
        if (t + 1 < nt) LOAD_REGS((t + 1) * BKt);                              \
        _Pragma("unroll")                                                      \
        for (int kk = 0; kk < BKt; kk += 16) {                                 \
            wmma::fragment<wmma::matrix_a, 16, 16, 16, __nv_bfloat16, wmma::row_major> ah[2], al[2]; \
            wmma::fragment<wmma::matrix_b, 16, 16, 16, __nv_bfloat16, wmma::col_major> bh[2], bl[2]; \
            _Pragma("unroll")                                                  \
            for (int i = 0; i < 2; i++) {                                      \
                const __nv_bfloat16* pa = AHI(pp) + (wm * 32 + i * 16) * PADt + kk; \
                wmma::load_matrix_sync(ah[i], pa, PADt);                       \
                wmma::load_matrix_sync(al[i], pa + BMt * PADt, PADt);          \
            }                                                                  \
            _Pragma("unroll")                                                  \
            for (int j = 0; j < 2; j++) {                                      \
                const __nv_bfloat16* pb = BHI(pp) + (wn * 32 + j * 16) * PADt + kk; \
                wmma::load_matrix_sync(bh[j], pb, PADt);                       \
                wmma::load_matrix_sync(bl[j], pb + BNt * PADt, PADt);          \
            }                                                                  \
            _Pragma("unroll")                                                  \
            for (int i = 0; i < 2; i++)                                        \
                _Pragma("unroll")                                              \
                for (int j = 0; j < 2; j++) {                                  \
                    wmma::mma_sync(acc[i][j], ah[i], bh[j], acc[i][j]);        \
                    wmma::mma_sync(acc[i][j], ah[i], bl[j], acc[i][j]);        \
                    wmma::mma_sync(acc[i][j], al[i], bh[j], acc[i][j]);        \
                }                                                              \
        }                                                                      \
        if (t + 1 < nt) STAGE(1 - pp);                                         \
        __syncthreads();                                                       \
    }

#define PATCH_STORE()                                                          \
    {                                                                          \
        _Pragma("unroll")                                                      \
        for (int i = 0; i < 2; i++)                                            \
            _Pragma("unroll")                                                  \
            for (int j = 0; j < 2; j++)                                        \
                wmma::store_matrix_sync(patch + i * 16 * 32 + j * 16,          \
                                        acc[i][j], 32, wmma::mem_row_major);   \
        __syncwarp();                                                          \
    }

// ================= main GEMM =================
// modes: 0=C ; 1=maxpool into mp ; 2=C+mu/lv ; 3=C+plv ; 4=dmu/dlv/z2 (no C)
__global__ __launch_bounds__(256) void k_wgemm(
    const float* __restrict__ Ap, int lda,
    const float* __restrict__ Wp, int K,
    const float* __restrict__ bias,
    float* __restrict__ C, int N, int act, int mode,
    unsigned int* __restrict__ mp,
    float* __restrict__ aux0, float* __restrict__ aux1,
    const float* __restrict__ paux, float* __restrict__ z2out)
{
    const int ldw = K;
    extern __shared__ char smem[];

    const int tid = threadIdx.x, wid = tid >> 5, lid = tid & 31;
    const int bm = blockIdx.y * BMt, bn = blockIdx.x * BNt;
    const int wm = wid & 3, wn = wid >> 2;     // 4 x 2 warps, 32x32 each
    const int arow = tid >> 3, ak4 = tid & 7;

    float4 ar[4], br[2];
    wmma::fragment<wmma::accumulator, 16, 16, 16, float> acc[2][2];
#pragma unroll
    for (int i = 0; i < 2; i++)
#pragma unroll
        for (int j = 0; j < 2; j++)
            wmma::fill_fragment(acc[i][j], 0.0f);

    const int nt = K / BKt;
    MAINLOOP();

    float* patch = reinterpret_cast<float*>(smem) + wid * 1024;
    PATCH_STORE();

    const int cbase = bn + wn * 32;
    const int c0 = (lid & 7) * 4;

    if (mode == 1) {
        float mx[4] = {-CUDART_INF_F, -CUDART_INF_F, -CUDART_INF_F, -CUDART_INF_F};
#pragma unroll
        for (int it = 0; it < 8; it++) {
            int r = it * 4 + (lid >> 3);
#pragma unroll
            for (int j = 0; j < 4; j++) {
                float rr = patch[r * 32 + c0 + j] + __ldg(&bias[cbase + c0 + j]);
                rr = rr > 0.f ? rr : 0.2f * rr;
                mx[j] = fmaxf(mx[j], rr);
            }
        }
        int b = (bm + wm * 32) >> 6;
#pragma unroll
        for (int j = 0; j < 4; j++)
            atomicMax(&mp[b * N + cbase + c0 + j], f32_ordered(mx[j]));
        return;
    }

#pragma unroll
    for (int it = 0; it < 8; it++) {
        int r = it * 4 + (lid >> 3);
        int m = bm + wm * 32 + r;
        int n = cbase + c0;
        float4 v;
        float* vp = reinterpret_cast<float*>(&v);
#pragma unroll
        for (int j = 0; j < 4; j++) {
            float rr = patch[r * 32 + c0 + j] + __ldg(&bias[n + j]);
            if (act) rr = rr > 0.f ? rr : 0.2f * rr;
            vp[j] = rr;
        }
        if (mode != 4)
            *reinterpret_cast<float4*>(&C[(size_t)m * N + n]) = v;
        if (mode == 2) {
            if (n < 256)
                *reinterpret_cast<float4*>(&aux0[m * 256 + n]) = v;
            else
                *reinterpret_cast<float4*>(&aux1[m * 256 + n - 256]) = v;
        } else if (mode == 3) {
            if (n >= 768)
                *reinterpret_cast<float4*>(&aux0[m * 768 + n - 768]) = v;
        } else if (mode == 4) {
            if (n < 768) {
                *reinterpret_cast<float4*>(&aux0[m * 768 + n]) = v;
                float4 pv = *reinterpret_cast<const float4*>(&paux[(size_t)m * 1536 + n]);
                float4 z;
                z.x = v.x + pv.x; z.y = v.y + pv.y;
                z.z = v.z + pv.z; z.w = v.w + pv.w;
                *reinterpret_cast<float4*>(&z2out[m * 768 + n]) = z;
            } else {
                *reinterpret_cast<float4*>(&aux1[m * 768 + n - 768]) = v;
            }
        }
    }
}

// ================= tensorized dist + argmin (batched over 4 bn tiles) =======
// grid (4, 4, 64), block 256; each CTA handles bn tiles blockIdx.x*4 .. +3
__global__ __launch_bounds__(256) void k_distw(
    const float* __restrict__ recon,
    const float* __restrict__ book,
    const float* __restrict__ xr2,
    const float* __restrict__ book2,
    float* __restrict__ dist,
    unsigned long long* __restrict__ keys)
{
    extern __shared__ char smem[];

    const int tid = threadIdx.x, wid = tid >> 5, lid = tid & 31;
    const int c = blockIdx.z;
    const int bm = blockIdx.y * BMt;
    const int wm = wid & 3, wn = wid >> 2;
    const int arow = tid >> 3, ak4 = tid & 7;

    const float* Ap = recon + c * 64;
    const float* Wp = book + (size_t)c * 65536;
    const int lda = 4096, ldw = 64;

    for (int bi = 0; bi < 4; bi++) {
        const int bn = (blockIdx.x * 4 + bi) * BNt;
        if (bi > 0) __syncthreads();   // patch region overlaps stage smem

        float4 ar[4], br[2];
        wmma::fragment<wmma::accumulator, 16, 16, 16, float> acc[2][2];
#pragma unroll
        for (int i = 0; i < 2; i++)
#pragma unroll
            for (int j = 0; j < 2; j++)
                wmma::fill_fragment(acc[i][j], 0.0f);

        const int nt = 2;
        MAINLOOP();

        float* patch = reinterpret_cast<float*>(smem) + wid * 1024;
        PATCH_STORE();

        const int sbase = bn + wn * 32;
        const int c0 = (lid & 7) * 4;

#pragma unroll
        for (int it = 0; it < 8; it++) {
            int r = it * 4 + (lid >> 3);
            int m = bm + wm * 32 + r;
            int s = sbase + c0;
            float x2 = __ldg(&xr2[m * 64 + c]);
            float4 v;
            float* vp = reinterpret_cast<float*>(&v);
            unsigned long long kbest = ~0ull;
#pragma unroll
            for (int j = 0; j < 4; j++) {
                float dval = x2 + __ldg(&book2[c * 1024 + s + j])
                           - 2.0f * patch[r * 32 + c0 + j];
                vp[j] = dval;
                unsigned long long key =
                    ((unsigned long long)f32_ordered(dval) << 32) | (unsigned int)(s + j);
                kbest = min(kbest, key);
            }
            *reinterpret_cast<float4*>(&dist[((size_t)m * 64 + c) * 1024 + s]) = v;
#pragma unroll
            for (int off = 4; off; off >>= 1) {
                unsigned long long o = __shfl_xor_sync(0xffffffffu, kbest, off, 8);
                kbest = min(kbest, o);
            }
            if ((lid & 7) == 0) atomicMin(&keys[m * 64 + c], kbest);
        }
    }
}

// ================= elementwise helpers =================
__global__ void k_init(unsigned int* __restrict__ hmaxu,
                       unsigned long long* __restrict__ keys,
                       const float* __restrict__ book,
                       float* __restrict__ book2)
{
    int idx = blockIdx.x * blockDim.x + threadIdx.x;
    if (idx < 512 * 512) hmaxu[idx] = f32_ordered(-CUDART_INF_F);
    if (idx < 512 * 64)  keys[idx] = ~0ull;
    if (idx < 64 * 1024) {
        const float4* p = reinterpret_cast<const float4*>(book + (size_t)idx * 64);
        float s = 0.f;
#pragma unroll
        for (int i = 0; i < 16; i++) {
            float4 v = p[i];
            s += v.x * v.x + v.y * v.y + v.z * v.z + v.w * v.w;
        }
        book2[idx] = s;
    }
}

__global__ void k_cvthmax(const unsigned int* __restrict__ hmaxu, float* __restrict__ hmax)
{
    int idx = blockIdx.x * blockDim.x + threadIdx.x;
    if (idx < 512 * 512) hmax[idx] = f32_unordered(hmaxu[idx]);
}

__global__ void k_cat(const float* __restrict__ z1, const float* __restrict__ h,
                      float* __restrict__ dst)
{
    int idx = blockIdx.x * blockDim.x + threadIdx.x;
    if (idx >= 512 * 2304) return;
    int b = idx / 2304, j = idx - b * 2304;
    dst[idx] = (j < 256) ? z1[(size_t)b * 512 + j] : h[(size_t)b * 2048 + (j - 256)];
}

__global__ void k_rowsq(const float* __restrict__ src, float* __restrict__ dst, int nrows)
{
    int idx = blockIdx.x * blockDim.x + threadIdx.x;
    if (idx >= nrows) return;
    const float4* p = reinterpret_cast<const float4*>(src + (size_t)idx * 64);
    float s = 0.f;
#pragma unroll
    for (int i = 0; i < 16; i++) {
        float4 v = p[i];
        s += v.x * v.x + v.y * v.y + v.z * v.z + v.w * v.w;
    }
    dst[idx] = s;
}

__global__ void k_writeidx(const unsigned long long* __restrict__ keys,
                           float* __restrict__ out)
{
    int idx = blockIdx.x * blockDim.x + threadIdx.x;
    if (idx < 512 * 64)
        out[idx] = (float)(unsigned int)(keys[idx] & 0xFFFFFFFFull);
}

// ================= launcher =================
#define GEMM_SMEM 61440

extern "C" void kernel_launch(void* const* d_in, const int* in_sizes, int n_in,
                              void* d_out, int out_size)
{
    const float* x        = (const float*)d_in[0];
    const float* codebook = (const float*)d_in[1];
    const float* enc_w1   = (const float*)d_in[2];
    const float* enc_b1   = (const float*)d_in[3];
    const float* enc_w2   = (const float*)d_in[4];
    const float* enc_b2   = (const float*)d_in[5];
    const float* inf1_w   = (const float*)d_in[6];
    const float* inf1_b   = (const float*)d_in[7];
    const float* inf2_w1  = (const float*)d_in[8];
    const float* inf2_b1  = (const float*)d_in[9];
    const float* inf2_w2  = (const float*)d_in[10];
    const float* inf2_b2  = (const float*)d_in[11];
    const float* prior_w1 = (const float*)d_in[12];
    const float* prior_b1 = (const float*)d_in[13];
    const float* prior_w2 = (const float*)d_in[14];
    const float* prior_b2 = (const float*)d_in[15];
    const float* dec_w1   = (const float*)d_in[16];
    const float* dec_b1   = (const float*)d_in[17];
    const float* dec_w2   = (const float*)d_in[18];
    const float* dec_b2   = (const float*)d_in[19];
    float* out = (float*)d_out;

    float *hmax, *h2, *h3, *t, *p, *cat, *z2, *xr2, *book2;
    unsigned int* hmaxu;
    unsigned long long* keys;
    cudaGetSymbolAddress((void**)&hmaxu, g_hmaxu);
    cudaGetSymbolAddress((void**)&hmax,  g_hmax);
    cudaGetSymbolAddress((void**)&h2,    g_h2);
    cudaGetSymbolAddress((void**)&h3,    g_h3);
    cudaGetSymbolAddress((void**)&t,     g_t);
    cudaGetSymbolAddress((void**)&p,     g_p);
    cudaGetSymbolAddress((void**)&cat,   g_cat);
    cudaGetSymbolAddress((void**)&z2,    g_z2);
    cudaGetSymbolAddress((void**)&xr2,   g_xr2);
    cudaGetSymbolAddress((void**)&book2, g_book2);
    cudaGetSymbolAddress((void**)&keys,  g_keys);

    cudaFuncSetAttribute(k_wgemm, cudaFuncAttributeMaxDynamicSharedMemorySize, GEMM_SMEM);
    cudaFuncSetAttribute(k_distw, cudaFuncAttributeMaxDynamicSharedMemorySize, GEMM_SMEM);

    // 0) fused init
    k_init<<<(512*512+255)/256, 256>>>(hmaxu, keys, codebook, book2);
    // 1) enc1 + fused maxpool (2048 CTAs)
    k_wgemm<<<dim3(512/64, 32768/128), 256, GEMM_SMEM>>>(
        x, 64, enc_w1, 64, enc_b1, nullptr, 512, 1, 1, hmaxu, nullptr, nullptr, nullptr, nullptr);
    k_cvthmax<<<(512*512+255)/256, 256>>>(hmaxu, hmax);
    // 2) enc2
    k_wgemm<<<dim3(2048/64, 4), 256, GEMM_SMEM>>>(
        hmax, 512, enc_w2, 512, enc_b2, h2, 2048, 0, 0, nullptr, nullptr, nullptr, nullptr, nullptr);
    // 3) inf1 (+ mu/lv)
    k_wgemm<<<dim3(512/64, 4), 256, GEMM_SMEM>>>(
        h2, 2048, inf1_w, 2048, inf1_b, h3, 512, 0, 2, nullptr,
        out + OFF_MU, out + OFF_LV, nullptr, nullptr);
    // 4) prior
    k_wgemm<<<dim3(2048/64, 4), 256, GEMM_SMEM>>>(
        h3, 512, prior_w1, 256, prior_b1, t, 2048, 1, 0, nullptr, nullptr, nullptr, nullptr, nullptr);
    k_wgemm<<<dim3(1536/64, 4), 256, GEMM_SMEM>>>(
        t, 2048, prior_w2, 2048, prior_b2, p, 1536, 0, 3, nullptr,
        out + OFF_PLV, nullptr, nullptr, nullptr);
    // 5) inf2
    k_cat<<<(512*2304+255)/256, 256>>>(h3, h2, cat);
    k_wgemm<<<dim3(2048/64, 4), 256, GEMM_SMEM>>>(
        cat, 2304, inf2_w1, 2304, inf2_b1, t, 2048, 1, 0, nullptr, nullptr, nullptr, nullptr, nullptr);
    k_wgemm<<<dim3(1536/64, 4), 256, GEMM_SMEM>>>(
        t, 2048, inf2_w2, 2048, inf2_b2, nullptr, 1536, 0, 4, nullptr,
        out + OFF_DMU, out + OFF_DLV, p, z2);
    // 6) decoder
    k_wgemm<<<dim3(2048/64, 4), 256, GEMM_SMEM>>>(
        z2, 768, dec_w1, 768, dec_b1, t, 2048, 1, 0, nullptr, nullptr, nullptr, nullptr, nullptr);
    k_wgemm<<<dim3(4096/64, 4), 256, GEMM_SMEM>>>(
        t, 2048, dec_w2, 2048, dec_b2, out + OFF_RECON, 4096, 0, 0, nullptr, nullptr, nullptr, nullptr, nullptr);
    // 7) dist + argmin (batched 4 bn tiles per CTA)
    k_rowsq<<<(512*64+255)/256, 256>>>(out + OFF_RECON, xr2, 512*64);
    k_distw<<<dim3(4, 4, 64), 256, GEMM_SMEM>>>(
        out + OFF_RECON, codebook, xr2, book2, out + OFF_DIST, keys);
    k_writeidx<<<(512*64+255)/256, 256>>>(keys, out + OFF_IDX);
}

// round 16
// speedup vs baseline: 1.2441x; 1.0453x over previous
#include <cuda_runtime.h>
#include <cuda_bf16.h>
#include <math_constants.h>
#include <mma.h>
#include <cstdint>

using namespace nvcuda;

// ---------------- output packing ----------------
#define LEN_RECON (512*4096)
#define LEN_DIST  (512*64*1024)
#define LEN_IDX   (512*64)
#define LEN_MU    (512*256)
#define LEN_LV    (512*256)
#define LEN_DMU   (512*768)
#define LEN_DLV   (512*768)

#define OFF_RECON 0
#define OFF_DIST  (OFF_RECON + LEN_RECON)
#define OFF_IDX   (OFF_DIST  + LEN_DIST)
#define OFF_MU    (OFF_IDX   + LEN_IDX)
#define OFF_LV    (OFF_MU    + LEN_MU)
#define OFF_DMU   (OFF_LV    + LEN_LV)
#define OFF_DLV   (OFF_DMU   + LEN_DMU)
#define OFF_PLV   (OFF_DLV   + LEN_DLV)

// ---------------- scratch ----------------
__device__ unsigned int g_hmaxu[512 * 512];
__device__ float g_hmax[512 * 512];
__device__ float g_h2[512 * 2048];
__device__ float g_h3[512 * 512];
__device__ float g_t[512 * 2048];
__device__ float g_tp[512 * 2048];
__device__ float g_p[512 * 1536];
__device__ float g_d[512 * 1536];
__device__ float g_cat[512 * 2304];
__device__ float g_xr2[512 * 64];
__device__ float g_book2[64 * 1024];
__device__ unsigned long long g_keys[512 * 64];

__device__ __forceinline__ unsigned int f32_ordered(float f)
{
    unsigned int b = __float_as_uint(f);
    return (b & 0x80000000u) ? ~b : (b | 0x80000000u);
}
__device__ __forceinline__ float f32_unordered(unsigned int u)
{
    return __uint_as_float((u & 0x80000000u) ? (u & 0x7FFFFFFFu) : ~u);
}

// ================ GEMM building blocks (256 thr, 8 warps, 32x32 warp tile) ====
#define BMt 128
#define BNt 64
#define BKt 32
#define PADt 40
#define STG_BYTES 30720
#define GEMM_SMEM 61440

#define AHI(s) (reinterpret_cast<__nv_bfloat16*>(smem + (s) * STG_BYTES))
#define ALO(s) (AHI(s) + BMt * PADt)
#define BHI(s) (ALO(s) + BMt * PADt)
#define BLO(s) (BHI(s) + BNt * PADt)

#define CVT_ST(hiP, loP, r, v)                                                 \
    {                                                                          \
        __nv_bfloat16 hx = __float2bfloat16((v).x);                            \
        __nv_bfloat16 hy = __float2bfloat16((v).y);                            \
        __nv_bfloat16 hz = __float2bfloat16((v).z);                            \
        __nv_bfloat16 hw = __float2bfloat16((v).w);                            \
        __nv_bfloat16* ph = (hiP) + (r) * PADt + ak4 * 4;                      \
        *reinterpret_cast<__nv_bfloat162*>(ph)     = __halves2bfloat162(hx, hy); \
        *reinterpret_cast<__nv_bfloat162*>(ph + 2) = __halves2bfloat162(hz, hw); \
        __nv_bfloat16* pl = (loP) + (r) * PADt + ak4 * 4;                      \
        *reinterpret_cast<__nv_bfloat162*>(pl) = __halves2bfloat162(           \
            __float2bfloat16((v).x - __bfloat162float(hx)),                    \
            __float2bfloat16((v).y - __bfloat162float(hy)));                   \
        *reinterpret_cast<__nv_bfloat162*>(pl + 2) = __halves2bfloat162(       \
            __float2bfloat16((v).z - __bfloat162float(hz)),                    \
            __float2bfloat16((v).w - __bfloat162float(hw)));                   \
    }

#define STAGE(s)                                                               \
    {                                                                          \
        _Pragma("unroll")                                                      \
        for (int i = 0; i < 4; i++) CVT_ST(AHI(s), ALO(s), arow + i * 32, ar[i]); \
        _Pragma("unroll")                                                      \
        for (int i = 0; i < 2; i++) CVT_ST(BHI(s), BLO(s), arow + i * 32, br[i]); \
    }

#define MAINLOOP(LOADM)                                                        \
    LOADM(0);                                                                  \
    STAGE(0);                                                                  \
    __syncthreads();                                                           \
    for (int t = 0; t < nt; t++) {                                             \
        const int pp = t & 1;                                                  \
        if (t + 1 < nt) LOADM((t + 1) * BKt);                                  \
        _Pragma("unroll")                                                      \
        for (int kk = 0; kk < BKt; kk += 16) {                                 \
            wmma::fragment<wmma::matrix_a, 16, 16, 16, __nv_bfloat16, wmma::row_major> ah[2], al[2]; \
            wmma::fragment<wmma::matrix_b, 16, 16, 16, __nv_bfloat16, wmma::col_major> bh[2], bl[2]; \
            _Pragma("unroll")                                                  \
            for (int i = 0; i < 2; i++) {                                      \
                const __nv_bfloat16* pa = AHI(pp) + (wm * 32 + i * 16) * PADt + kk; \
                wmma::load_matrix_sync(ah[i], pa, PADt);                       \
                wmma::load_matrix_sync(al[i], pa + BMt * PADt, PADt);          \
            }                                                                  \
            _Pragma("unroll")                                                  \
            for (int j = 0; j < 2; j++) {                                      \
                const __nv_bfloat16* pb = BHI(pp) + (wn * 32 + j * 16) * PADt + kk; \
                wmma::load_matrix_sync(bh[j], pb, PADt);                       \
                wmma::load_matrix_sync(bl[j], pb + BNt * PADt, PADt);          \
            }                                                                  \
            _Pragma("unroll")                                                  \
            for (int i = 0; i < 2; i++)                                        \
                _Pragma("unroll")                                              \
                for (int j = 0; j < 2; j++) {                                  \
                    wmma::mma_sync(acc[i][j], ah[i], bh[j], acc[i][j]);        \
                    wmma::mma_sync(acc[i][j], ah[i], bl[j], acc[i][j]);        \
                    wmma::mma_sync(acc[i][j], al[i], bh[j], acc[i][j]);        \
                }                                                              \
        }                                                                      \
        if (t + 1 < nt) STAGE(1 - pp);                                         \
        __syncthreads();                                                       \
    }

#define PATCH_STORE()                                                          \
    {                                                                          \
        _Pragma("unroll")                                                      \
        for (int i = 0; i < 2; i++)                                            \
            _Pragma("unroll")                                                  \
            for (int j = 0; j < 2; j++)                                        \
                wmma::store_matrix_sync(patch + i * 16 * 32 + j * 16,          \
                                        acc[i][j], 32, wmma::mem_row_major);   \
        __syncwarp();                                                          \
    }

#define GEMM_PRELUDE()                                                         \
    extern __shared__ char smem[];                                             \
    const int tid = threadIdx.x, wid = tid >> 5, lid = tid & 31;               \
    const int bm = blockIdx.y * BMt, bn = blockIdx.x * BNt;                    \
    const int wm = wid & 3, wn = wid >> 2;                                     \
    const int arow = tid >> 3, ak4 = tid & 7;                                  \
    float4 ar[4], br[2];                                                       \
    wmma::fragment<wmma::accumulator, 16, 16, 16, float> acc[2][2];            \
    _Pragma("unroll")                                                          \
    for (int i = 0; i < 2; i++)                                                \
        _Pragma("unroll")                                                      \
        for (int j = 0; j < 2; j++)                                            \
            wmma::fill_fragment(acc[i][j], 0.0f);

// ================= main GEMM =================
// modes: 0 = store C (bias+act) ; 1 = maxpool into mp ; 6 = atomicAdd into C
// split-K: koff = blockIdx.z * K ; Kfull = W row stride
#define LOAD_REGS(k0)                                                          \
    {                                                                          \
        _Pragma("unroll")                                                      \
        for (int i = 0; i < 4; i++)                                            \
            ar[i] = *reinterpret_cast<const float4*>(                          \
                &Ap[(size_t)(bm + arow + i * 32) * lda + koff + (k0) + ak4 * 4]); \
        _Pragma("unroll")                                                      \
        for (int i = 0; i < 2; i++)                                            \
            br[i] = *reinterpret_cast<const float4*>(                          \
                &Wp[(size_t)(bn + arow + i * 32) * Kfull + koff + (k0) + ak4 * 4]); \
    }

__global__ __launch_bounds__(256) void k_wgemm(
    const float* __restrict__ Ap, int lda,
    const float* __restrict__ Wp, int K, int Kfull,
    const float* __restrict__ bias,
    float* __restrict__ C, int N, int act, int mode,
    unsigned int* __restrict__ mp)
{
    GEMM_PRELUDE();
    const int koff = blockIdx.z * K;
    const int nt = K / BKt;
    MAINLOOP(LOAD_REGS);

    float* patch = reinterpret_cast<float*>(smem) + wid * 1024;
    PATCH_STORE();

    const int cbase = bn + wn * 32;
    const int c0 = (lid & 7) * 4;

    if (mode == 1) {
        float mx[4] = {-CUDART_INF_F, -CUDART_INF_F, -CUDART_INF_F, -CUDART_INF_F};
#pragma unroll
        for (int it = 0; it < 8; it++) {
            int r = it * 4 + (lid >> 3);
#pragma unroll
            for (int j = 0; j < 4; j++) {
                float rr = patch[r * 32 + c0 + j] + __ldg(&bias[cbase + c0 + j]);
                rr = rr > 0.f ? rr : 0.2f * rr;
                mx[j] = fmaxf(mx[j], rr);
            }
        }
        int b = (bm + wm * 32) >> 6;
#pragma unroll
        for (int j = 0; j < 4; j++)
            atomicMax(&mp[b * N + cbase + c0 + j], f32_ordered(mx[j]));
        return;
    }

    if (mode == 6) {
#pragma unroll
        for (int it = 0; it < 8; it++) {
            int r = it * 4 + (lid >> 3);
            int m = bm + wm * 32 + r;
            int n = cbase + c0;
#pragma unroll
            for (int j = 0; j < 4; j++)
                atomicAdd(&C[(size_t)m * N + n + j], patch[r * 32 + c0 + j]);
        }
        return;
    }

#pragma unroll
    for (int it = 0; it < 8; it++) {
        int r = it * 4 + (lid >> 3);
        int m = bm + wm * 32 + r;
        int n = cbase + c0;
        float4 v;
        float* vp = reinterpret_cast<float*>(&v);
#pragma unroll
        for (int j = 0; j < 4; j++) {
            float rr = patch[r * 32 + c0 + j] + __ldg(&bias[n + j]);
            if (act) rr = rr > 0.f ? rr : 0.2f * rr;
            vp[j] = rr;
        }
        *reinterpret_cast<float4*>(&C[(size_t)m * N + n]) = v;
    }
}

// ================= sum-loader GEMM (dec1: A = d_mu + p_mu) =================
#define LOAD_REGS_S(k0)                                                        \
    {                                                                          \
        _Pragma("unroll")                                                      \
        for (int i = 0; i < 4; i++) {                                          \
            int m = bm + arow + i * 32;                                        \
            float4 u = *reinterpret_cast<const float4*>(                       \
                &Ap[(size_t)m * lda + (k0) + ak4 * 4]);                        \
            float4 w2 = *reinterpret_cast<const float4*>(                      \
                &Ap2[(size_t)m * lda + (k0) + ak4 * 4]);                       \
            ar[i] = make_float4(u.x + w2.x, u.y + w2.y, u.z + w2.z, u.w + w2.w); \
        }                                                                      \
        _Pragma("unroll")                                                      \
        for (int i = 0; i < 2; i++)                                            \
            br[i] = *reinterpret_cast<const float4*>(                          \
                &Wp[(size_t)(bn + arow + i * 32) * K + (k0) + ak4 * 4]);       \
    }

__global__ __launch_bounds__(256) void k_wgemm_sum(
    const float* __restrict__ Ap, const float* __restrict__ Ap2, int lda,
    const float* __restrict__ Wp, int K,
    const float* __restrict__ bias,
    float* __restrict__ C, int N, int act)
{
    GEMM_PRELUDE();
    const int nt = K / BKt;
    MAINLOOP(LOAD_REGS_S);

    float* patch = reinterpret_cast<float*>(smem) + wid * 1024;
    PATCH_STORE();

    const int cbase = bn + wn * 32;
    const int c0 = (lid & 7) * 4;
#pragma unroll
    for (int it = 0; it < 8; it++) {
        int r = it * 4 + (lid >> 3);
        int m = bm + wm * 32 + r;
        int n = cbase + c0;
        float4 v;
        float* vp = reinterpret_cast<float*>(&v);
#pragma unroll
        for (int j = 0; j < 4; j++) {
            float rr = patch[r * 32 + c0 + j] + __ldg(&bias[n + j]);
            if (act) rr = rr > 0.f ? rr : 0.2f * rr;
            vp[j] = rr;
        }
        *reinterpret_cast<float4*>(&C[(size_t)m * N + n]) = v;
    }
}

// ================= tensorized dist + argmin (R10-identical) =================
#define LOAD_REGS_D(k0)                                                        \
    {                                                                          \
        _Pragma("unroll")                                                      \
        for (int i = 0; i < 4; i++)                                            \
            ar[i] = *reinterpret_cast<const float4*>(                          \
                &Ap[(size_t)(bm + arow + i * 32) * 4096 + (k0) + ak4 * 4]);    \
        _Pragma("unroll")                                                      \
        for (int i = 0; i < 2; i++)                                            \
            br[i] = *reinterpret_cast<const float4*>(                          \
                &Wp[(size_t)(bn + arow + i * 32) * 64 + (k0) + ak4 * 4]);      \
    }

__global__ __launch_bounds__(256) void k_distw(
    const float* __restrict__ recon,
    const float* __restrict__ book,
    const float* __restrict__ xr2,
    const float* __restrict__ book2,
    float* __restrict__ dist,
    unsigned long long* __restrict__ keys)
{
    GEMM_PRELUDE();
    const int c = blockIdx.z;
    const float* Ap = recon + c * 64;
    const float* Wp = book + (size_t)c * 65536;

    const int nt = 2;
    MAINLOOP(LOAD_REGS_D);

    float* patch = reinterpret_cast<float*>(smem) + wid * 1024;
    PATCH_STORE();

    const int sbase = bn + wn * 32;
    const int c0 = (lid & 7) * 4;

#pragma unroll
    for (int it = 0; it < 8; it++) {
        int r = it * 4 + (lid >> 3);
        int m = bm + wm * 32 + r;
        int s = sbase + c0;
        float x2 = __ldg(&xr2[m * 64 + c]);
        float4 v;
        float* vp = reinterpret_cast<float*>(&v);
        unsigned long long kbest = ~0ull;
#pragma unroll
        for (int j = 0; j < 4; j++) {
            float dval = x2 + __ldg(&book2[c * 1024 + s + j])
                       - 2.0f * patch[r * 32 + c0 + j];
            vp[j] = dval;
            unsigned long long key =
                ((unsigned long long)f32_ordered(dval) << 32) | (unsigned int)(s + j);
            kbest = min(kbest, key);
        }
        *reinterpret_cast<float4*>(&dist[((size_t)m * 64 + c) * 1024 + s]) = v;
#pragma unroll
        for (int off = 4; off; off >>= 1) {
            unsigned long long o = __shfl_xor_sync(0xffffffffu, kbest, off, 8);
            kbest = min(kbest, o);
        }
        if ((lid & 7) == 0) atomicMin(&keys[m * 64 + c], kbest);
    }
}

// ================= init: hmaxu, keys, book2, bias-init h3/p/d =================
__global__ void k_init(unsigned int* __restrict__ hmaxu,
                       unsigned long long* __restrict__ keys,
                       const float* __restrict__ book,
                       float* __restrict__ book2,
                       float* __restrict__ h3, const float* __restrict__ inf1_b,
                       float* __restrict__ p,  const float* __restrict__ prior_b2,
                       float* __restrict__ d,  const float* __restrict__ inf2_b2)
{
    int idx = blockIdx.x * blockDim.x + threadIdx.x;   // up to 512*1536*... use grid
    if (idx < 512 * 512) {
        hmaxu[idx] = f32_ordered(-CUDART_INF_F);
        h3[idx] = __ldg(&inf1_b[idx & 511]);
    }
    if (idx < 512 * 64) keys[idx] = ~0ull;
    if (idx < 64 * 1024) {
        const float4* pp = reinterpret_cast<const float4*>(book + (size_t)idx * 64);
        float s = 0.f;
#pragma unroll
        for (int i = 0; i < 16; i++) {
            float4 v = pp[i];
            s += v.x * v.x + v.y * v.y + v.z * v.z + v.w * v.w;
        }
        book2[idx] = s;
    }
    if (idx < 512 * 1536) {
        int n = idx % 1536;
        p[idx] = __ldg(&prior_b2[n]);
        d[idx] = __ldg(&inf2_b2[n]);
    }
}

// ================= post: slice copies =================
__global__ void k_post(const float* __restrict__ h3,
                       const float* __restrict__ p,
                       const float* __restrict__ d,
                       float* __restrict__ out)
{
    int idx = blockIdx.x * blockDim.x + threadIdx.x;
    if (idx >= 512 * 768) return;
    int b = idx / 768, j = idx - b * 768;
    out[OFF_DMU + idx] = d[b * 1536 + j];
    out[OFF_DLV + idx] = d[b * 1536 + 768 + j];
    out[OFF_PLV + idx] = p[b * 1536 + 768 + j];
    if (j < 256) {
        out[OFF_MU + b * 256 + j] = h3[b * 512 + j];
        out[OFF_LV + b * 256 + j] = h3[b * 512 + 256 + j];
    }
}

// ================= elementwise helpers =================
__global__ void k_cvthmax(const unsigned int* __restrict__ hmaxu, float* __restrict__ hmax)
{
    int idx = blockIdx.x * blockDim.x + threadIdx.x;
    if (idx < 512 * 512) hmax[idx] = f32_unordered(hmaxu[idx]);
}

__global__ void k_cat(const float* __restrict__ z1, const float* __restrict__ h,
                      float* __restrict__ dst)
{
    int idx = blockIdx.x * blockDim.x + threadIdx.x;
    if (idx >= 512 * 2304) return;
    int b = idx / 2304, j = idx - b * 2304;
    dst[idx] = (j < 256) ? z1[(size_t)b * 512 + j] : h[(size_t)b * 2048 + (j - 256)];
}

__global__ void k_rowsq(const float* __restrict__ src, float* __restrict__ dst, int nrows)
{
    int idx = blockIdx.x * blockDim.x + threadIdx.x;
    if (idx >= nrows) return;
    const float4* p = reinterpret_cast<const float4*>(src + (size_t)idx * 64);
    float s = 0.f;
#pragma unroll
    for (int i = 0; i < 16; i++) {
        float4 v = p[i];
        s += v.x * v.x + v.y * v.y + v.z * v.z + v.w * v.w;
    }
    dst[idx] = s;
}

__global__ void k_writeidx(const unsigned long long* __restrict__ keys,
                           float* __restrict__ out)
{
    int idx = blockIdx.x * blockDim.x + threadIdx.x;
    if (idx < 512 * 64)
        out[idx] = (float)(unsigned int)(keys[idx] & 0xFFFFFFFFull);
}

// ================= launcher =================
extern "C" void kernel_launch(void* const* d_in, const int* in_sizes, int n_in,
                              void* d_out, int out_size)
{
    const float* x        = (const float*)d_in[0];
    const float* codebook = (const float*)d_in[1];
    const float* enc_w1   = (const float*)d_in[2];
    const float* enc_b1   = (const float*)d_in[3];
    const float* enc_w2   = (const float*)d_in[4];
    const float* enc_b2   = (const float*)d_in[5];
    const float* inf1_w   = (const float*)d_in[6];
    const float* inf1_b   = (const float*)d_in[7];
    const float* inf2_w1  = (const float*)d_in[8];
    const float* inf2_b1  = (const float*)d_in[9];
    const float* inf2_w2  = (const float*)d_in[10];
    const float* inf2_b2  = (const float*)d_in[11];
    const float* prior_w1 = (const float*)d_in[12];
    const float* prior_b1 = (const float*)d_in[13];
    const float* prior_w2 = (const float*)d_in[14];
    const float* prior_b2 = (const float*)d_in[15];
    const float* dec_w1   = (const float*)d_in[16];
    const float* dec_b1   = (const float*)d_in[17];
    const float* dec_w2   = (const float*)d_in[18];
    const float* dec_b2   = (const float*)d_in[19];
    float* out = (float*)d_out;

    float *hmax, *h2, *h3, *t, *tp, *p, *d, *cat, *xr2, *book2;
    unsigned int* hmaxu;
    unsigned long long* keys;
    cudaGetSymbolAddress((void**)&hmaxu, g_hmaxu);
    cudaGetSymbolAddress((void**)&hmax,  g_hmax);
    cudaGetSymbolAddress((void**)&h2,    g_h2);
    cudaGetSymbolAddress((void**)&h3,    g_h3);
    cudaGetSymbolAddress((void**)&t,     g_t);
    cudaGetSymbolAddress((void**)&tp,    g_tp);
    cudaGetSymbolAddress((void**)&p,     g_p);
    cudaGetSymbolAddress((void**)&d,     g_d);
    cudaGetSymbolAddress((void**)&cat,   g_cat);
    cudaGetSymbolAddress((void**)&xr2,   g_xr2);
    cudaGetSymbolAddress((void**)&book2, g_book2);
    cudaGetSymbolAddress((void**)&keys,  g_keys);

    cudaFuncSetAttribute(k_wgemm,     cudaFuncAttributeMaxDynamicSharedMemorySize, GEMM_SMEM);
    cudaFuncSetAttribute(k_wgemm_sum, cudaFuncAttributeMaxDynamicSharedMemorySize, GEMM_SMEM);
    cudaFuncSetAttribute(k_distw,     cudaFuncAttributeMaxDynamicSharedMemorySize, GEMM_SMEM);

    // 0) init: hmaxu, keys, book2, bias-init h3/p/d
    k_init<<<(512*1536+255)/256, 256>>>(hmaxu, keys, codebook, book2,
                                        h3, inf1_b, p, prior_b2, d, inf2_b2);
    // 1) enc1 + fused maxpool (2048 CTAs)
    k_wgemm<<<dim3(8, 256, 1), 256, GEMM_SMEM>>>(
        x, 64, enc_w1, 64, 64, enc_b1, nullptr, 512, 1, 1, hmaxu);
    k_cvthmax<<<(512*512+255)/256, 256>>>(hmaxu, hmax);
    // 2) enc2
    k_wgemm<<<dim3(32, 4, 1), 256, GEMM_SMEM>>>(
        hmax, 512, enc_w2, 512, 512, enc_b2, h2, 2048, 0, 0, nullptr);
    // 3) inf1 split-K=4 (atomic into bias-initialized h3)
    k_wgemm<<<dim3(8, 4, 4), 256, GEMM_SMEM>>>(
        h2, 2048, inf1_w, 512, 2048, nullptr, h3, 512, 0, 6, nullptr);
    // 4) prior1
    k_wgemm<<<dim3(32, 4, 1), 256, GEMM_SMEM>>>(
        h3, 512, prior_w1, 256, 256, prior_b1, tp, 2048, 1, 0, nullptr);
    // 5) prior2 split-K=4 (atomic into bias-initialized p)
    k_wgemm<<<dim3(24, 4, 4), 256, GEMM_SMEM>>>(
        tp, 2048, prior_w2, 512, 2048, nullptr, p, 1536, 0, 6, nullptr);
    // 6) inf2_1 (cat loader via k_cat)
    k_cat<<<(512*2304+255)/256, 256>>>(h3, h2, cat);
    k_wgemm<<<dim3(32, 4, 1), 256, GEMM_SMEM>>>(
        cat, 2304, inf2_w1, 2304, 2304, inf2_b1, t, 2048, 1, 0, nullptr);
    // 7) inf2_2 split-K=4 (atomic into bias-initialized d)
    k_wgemm<<<dim3(24, 4, 4), 256, GEMM_SMEM>>>(
        t, 2048, inf2_w2, 512, 2048, nullptr, d, 1536, 0, 6, nullptr);
    // 8) post: mu/lv/plv/dmu/dlv slices
    k_post<<<(512*768+255)/256, 256>>>(h3, p, d, out);
    // 9) dec1 (A = d_mu + p_mu via sum loader)
    k_wgemm_sum<<<dim3(32, 4, 1), 256, GEMM_SMEM>>>(
        d, p, 1536, dec_w1, 768, dec_b1, tp, 2048, 1);
    // 10) dec2
    k_wgemm<<<dim3(64, 4, 1), 256, GEMM_SMEM>>>(
        tp, 2048, dec_w2, 2048, 2048, dec_b2, out + OFF_RECON, 4096, 0, 0, nullptr);
    // 11) dist + argmin
    k_rowsq<<<(512*64+255)/256, 256>>>(out + OFF_RECON, xr2, 512*64);
    k_distw<<<dim3(16, 4, 64), 256, GEMM_SMEM>>>(
        out + OFF_RECON, codebook, xr2, book2, out + OFF_DIST, keys);
    k_writeidx<<<(512*64+255)/256, 256>>>(keys, out + OFF_IDX);
}